// round 12
// baseline (speedup 1.0000x reference)
#include <cuda_runtime.h>
#include <cuda_bf16.h>
#include <cstdint>

#define N_NODES 8192
#define IN_FEAT 128
#define OUT_FEAT 64
#define E_EDGES 131072
#define C2 128

// ---------------- device scratch (self-cleaning across graph replays) ----------------
__device__ int    g_deg[N_NODES];          // zero-init; k_scan_norm re-zeroes after use
__device__ int    g_off[N_NODES + 1];
__device__ int    g_cursor[N_NODES];
__device__ int    g_perm[E_EDGES];
__device__ float  g_norm[N_NODES];
__device__ float  g_X0[N_NODES * OUT_FEAT];        // pre-scaled by norm[row]
__device__ float  g_h1n[N_NODES * OUT_FEAT];
__device__ float  g_Y[N_NODES * C2];
__device__ float  g_z[N_NODES * OUT_FEAT];
__device__ __nv_bfloat16 g_zh[N_NODES * OUT_FEAT];
__device__ int    g_blkcnt[64];                    // per-128-node-block completion counters
__device__ unsigned long long g_flagword;          // bit b = z-block b ready
__device__ double g_edge_sum;
__device__ double g_sp_sum;

// ---------------- 1) degree count (+ reset sums, counters, flags) ----------------
__global__ void k_deg(const int* __restrict__ src) {
    int e = blockIdx.x * blockDim.x + threadIdx.x;
    if (e == 0) { g_edge_sum = 0.0; g_sp_sum = 0.0; g_flagword = 0ULL; }
    if (e < 64) g_blkcnt[e] = 0;
    if (e < E_EDGES) atomicAdd(&g_deg[src[e]], 1);
}

// ---------------- 2) scan + norm (+ self-clean g_deg) ----------------
__global__ void k_scan_norm() {
    __shared__ int part[1024];
    int tid = threadIdx.x;
    int base = tid * 8;
    int local[8], dv[8];
    int s = 0;
    #pragma unroll
    for (int j = 0; j < 8; j++) {
        dv[j] = g_deg[base + j];
        local[j] = s;
        s += dv[j];
        g_deg[base + j] = 0;
    }
    part[tid] = s;
    __syncthreads();
    for (int off = 1; off < 1024; off <<= 1) {
        int v = (tid >= off) ? part[tid - off] : 0;
        __syncthreads();
        part[tid] += v;
        __syncthreads();
    }
    int pre = (tid > 0) ? part[tid - 1] : 0;
    #pragma unroll
    for (int j = 0; j < 8; j++) {
        int o = pre + local[j];
        g_off[base + j] = o;
        g_cursor[base + j] = o;
        g_norm[base + j] = rsqrtf((float)(dv[j] < 1 ? 1 : dv[j]));
    }
    if (tid == 1023) g_off[N_NODES] = pre + s;
}

// ---------------- 3) fused: perm scatter + GEMM1 (X0 pre-scaled by norm[row]) ----------------
__global__ void __launch_bounds__(512) k_perm_gemm1(const int* __restrict__ src,
                                                    const int* __restrict__ dst,
                                                    const float* __restrict__ h,
                                                    const float* __restrict__ w0) {
    int tid = threadIdx.x;
    if (blockIdx.x < 1024) {
        __shared__ float ws[IN_FEAT][OUT_FEAT];
        __shared__ float hs[8][IN_FEAT];
        int row0 = blockIdx.x * 8;
        for (int t = tid; t < IN_FEAT * OUT_FEAT; t += 512)
            ws[t >> 6][t & 63] = w0[t];
        for (int t = tid; t < 8 * IN_FEAT; t += 512) {
            int r = t >> 7, k = t & 127;
            hs[r][k] = h[(row0 + r) * IN_FEAT + k];
        }
        __syncthreads();
        int r = tid >> 6, c = tid & 63;
        float acc = 0.f;
        #pragma unroll
        for (int k = 0; k < IN_FEAT; k++) acc = fmaf(hs[r][k], ws[k][c], acc);
        g_X0[(row0 + r) * OUT_FEAT + c] = acc * g_norm[row0 + r];
    } else {
        int e = (blockIdx.x - 1024) * 512 + tid;
        if (e < E_EDGES) {
            int p = atomicAdd(&g_cursor[src[e]], 1);
            g_perm[p] = dst[e];
        }
    }
}

// ---------------- 4) gather 1 (X0 already norm-scaled) ----------------
__global__ void k_gather1() {
    int w = (blockIdx.x * blockDim.x + threadIdx.x) >> 5;
    int lane = threadIdx.x & 31;
    if (w >= N_NODES) return;
    int beg = g_off[w], end = g_off[w + 1];
    float a0 = 0.f, a1 = 0.f;
    int e = beg;
    for (; e + 4 <= end; e += 4) {
        int d0 = g_perm[e], d1 = g_perm[e + 1], d2 = g_perm[e + 2], d3 = g_perm[e + 3];
        float x00 = g_X0[d0 * OUT_FEAT + lane], x01 = g_X0[d0 * OUT_FEAT + lane + 32];
        float x10 = g_X0[d1 * OUT_FEAT + lane], x11 = g_X0[d1 * OUT_FEAT + lane + 32];
        float x20 = g_X0[d2 * OUT_FEAT + lane], x21 = g_X0[d2 * OUT_FEAT + lane + 32];
        float x30 = g_X0[d3 * OUT_FEAT + lane], x31 = g_X0[d3 * OUT_FEAT + lane + 32];
        a0 += x00 + x10 + x20 + x30;
        a1 += x01 + x11 + x21 + x31;
    }
    for (; e < end; e++) {
        int d = g_perm[e];
        a0 += g_X0[d * OUT_FEAT + lane];
        a1 += g_X0[d * OUT_FEAT + lane + 32];
    }
    float nm = g_norm[w];
    g_h1n[w * OUT_FEAT + lane]      = fmaxf(a0 * nm, 0.f) * nm;
    g_h1n[w * OUT_FEAT + lane + 32] = fmaxf(a1 * nm, 0.f) * nm;
}

// ---------------- 5) GEMM 2 ----------------
__global__ void __launch_bounds__(1024) k_gemm2(const float* __restrict__ wmu,
                                                const float* __restrict__ wls) {
    __shared__ float ws[OUT_FEAT][C2];
    __shared__ float hs[8][OUT_FEAT];
    int tid = threadIdx.x;
    int row0 = blockIdx.x * 8;
    for (int t = tid; t < OUT_FEAT * OUT_FEAT; t += 1024) {
        int k = t >> 6, c = t & 63;
        ws[k][c]      = wmu[t];
        ws[k][c + 64] = wls[t];
    }
    for (int t = tid; t < 8 * OUT_FEAT; t += 1024) {
        int r = t >> 6, k = t & 63;
        hs[r][k] = g_h1n[(row0 + r) * OUT_FEAT + k];
    }
    __syncthreads();
    int r = tid >> 7, c = tid & 127;
    float acc = 0.f;
    #pragma unroll
    for (int k = 0; k < OUT_FEAT; k++) acc = fmaf(hs[r][k], ws[k][c], acc);
    g_Y[(row0 + r) * C2 + c] = acc;
}

// ---------------- 6) gather 2 + reparam + KL + bf16 pack + block-ready publication ----------------
__global__ void k_gather2(const float* __restrict__ eps, float* __restrict__ out) {
    int w = (blockIdx.x * blockDim.x + threadIdx.x) >> 5;
    int lane = threadIdx.x & 31;
    if (w >= N_NODES) return;
    int beg = g_off[w], end = g_off[w + 1];
    float m0 = 0.f, m1 = 0.f, l0 = 0.f, l1 = 0.f;
    int e = beg;
    for (; e + 2 <= end; e += 2) {
        int d0 = g_perm[e], d1 = g_perm[e + 1];
        const float* y0 = &g_Y[d0 * C2];
        const float* y1 = &g_Y[d1 * C2];
        float a0 = y0[lane], a1 = y0[lane + 32], a2 = y0[lane + 64], a3 = y0[lane + 96];
        float b0 = y1[lane], b1 = y1[lane + 32], b2 = y1[lane + 64], b3 = y1[lane + 96];
        m0 += a0 + b0; m1 += a1 + b1; l0 += a2 + b2; l1 += a3 + b3;
    }
    for (; e < end; e++) {
        const float* yr = &g_Y[g_perm[e] * C2];
        m0 += yr[lane];      m1 += yr[lane + 32];
        l0 += yr[lane + 64]; l1 += yr[lane + 96];
    }
    float nm = g_norm[w];
    m0 *= nm; m1 *= nm; l0 *= nm; l1 *= nm;
    float s0 = __expf(l0), s1 = __expf(l1);
    float z0 = m0 + s0 * eps[w * OUT_FEAT + lane];
    float z1 = m1 + s1 * eps[w * OUT_FEAT + lane + 32];
    g_z[w * OUT_FEAT + lane]      = z0;
    g_z[w * OUT_FEAT + lane + 32] = z1;
    g_zh[w * OUT_FEAT + lane]      = __float2bfloat16(z0);
    g_zh[w * OUT_FEAT + lane + 32] = __float2bfloat16(z1);
    out[w * OUT_FEAT + lane]      = -l0 + 0.5f * (s0 * s0 + m0 * m0 - 1.f);
    out[w * OUT_FEAT + lane + 32] = -l1 + 0.5f * (s1 * s1 + m1 * m1 - 1.f);

    // publish: z-block (w>>7) ready when all its 128 node-warps have committed
    __threadfence();
    __syncwarp();
    if (lane == 0) {
        int c = atomicAdd(&g_blkcnt[w >> 7], 1);
        if (c == 127) atomicOr(&g_flagword, 1ULL << (w >> 7));
    }
}

// ---------------- 7) edge term (runs on stream 0, overlapped under sp) ----------------
__global__ void k_edge(const int* __restrict__ src, const int* __restrict__ dst) {
    __shared__ float red[8];
    int wid = threadIdx.x >> 5, lane = threadIdx.x & 31;
    float acc = 0.f;
    for (int e = blockIdx.x * 8 + wid; e < E_EDGES; e += 64 * 8) {
        int s = src[e], d = dst[e];
        acc += g_z[s * OUT_FEAT + lane] * g_z[d * OUT_FEAT + lane]
             + g_z[s * OUT_FEAT + lane + 32] * g_z[d * OUT_FEAT + lane + 32];
    }
    #pragma unroll
    for (int o = 16; o; o >>= 1) acc += __shfl_xor_sync(0xffffffffu, acc, o);
    if (lane == 0) red[wid] = acc;
    __syncthreads();
    if (threadIdx.x == 0) {
        float s = 0.f;
        #pragma unroll
        for (int i = 0; i < 8; i++) s += red[i];
        atomicAdd(&g_edge_sum, (double)s);
    }
}

// ---------------- 8) persistent sp kernel (stream 1), flag-synced tiles ----------------
#define SROW 72
#define TILEB (128 * SROW)                 // bf16 elems per tile buffer (18 KB)
#define NTILES 2080
#define NBLK 296                           // 2 CTAs x 148 SMs, all resident
#define SP_SMEM (4 * TILEB * 2 + 256 * 4)  // 2xA + 2xB + red = 74752 B

__device__ __forceinline__ void cp16(void* sm, const void* gm) {
    uint32_t s = (uint32_t)__cvta_generic_to_shared(sm);
    asm volatile("cp.async.cg.shared.global [%0], [%1], 16;" :: "r"(s), "l"(gm));
}
__device__ __forceinline__ void mma_bf16(float* c, const uint32_t* a, const uint32_t* b) {
    asm volatile(
        "mma.sync.aligned.m16n8k16.row.col.f32.bf16.bf16.f32 "
        "{%0,%1,%2,%3}, {%4,%5,%6,%7}, {%8,%9}, {%0,%1,%2,%3};"
        : "+f"(c[0]), "+f"(c[1]), "+f"(c[2]), "+f"(c[3])
        : "r"(a[0]), "r"(a[1]), "r"(a[2]), "r"(a[3]), "r"(b[0]), "r"(b[1]));
}
__device__ __forceinline__ void map_tile(int b, int& ti, int& tj) {
    ti = (int)((129.0 - sqrt(129.0 * 129.0 - 8.0 * (double)b)) * 0.5);
    if (ti > 63) ti = 63;
    if (ti < 0) ti = 0;
    while (ti < 63 && (ti + 1) * (129 - (ti + 1)) / 2 <= b) ti++;
    while (ti > 0 && ti * (129 - ti) / 2 > b) ti--;
    tj = ti + (b - ti * (129 - ti) / 2);
}

__global__ void __launch_bounds__(256) k_sp() {
    extern __shared__ __nv_bfloat16 smp[];
    __nv_bfloat16* Ab = smp;                 // [2][TILEB]
    __nv_bfloat16* Bb = smp + 2 * TILEB;     // [2][TILEB]
    float* red = (float*)(smp + 4 * TILEB);

    int tid = threadIdx.x;
    int wid = tid >> 5, lane = tid & 31;
    unsigned long long cached = 0ULL;        // thread 0's local copy of flagword

    // wait-for-blocks helper (thread 0 polls, whole CTA barriers)
    auto waitbits = [&](int a, int b) {
        if (tid == 0) {
            unsigned long long need = (1ULL << a) | (1ULL << b);
            while ((cached & need) != need) {
                cached = atomicAdd(&g_flagword, 0ULL);
                if ((cached & need) != need) __nanosleep(128);
            }
        }
        __syncthreads();
    };

    int t = blockIdx.x;
    int ti, tj;
    map_tile(t, ti, tj);
    waitbits(ti, tj);
    {
        const __nv_bfloat16* ga = g_zh + (size_t)ti * 128 * 64;
        const __nv_bfloat16* gb = g_zh + (size_t)tj * 128 * 64;
        #pragma unroll
        for (int it = 0; it < 4; it++) {
            int q = tid + it * 256;
            int r = q >> 3, c = (q & 7) * 8;
            cp16(&Ab[r * SROW + c], ga + r * 64 + c);
            cp16(&Bb[r * SROW + c], gb + r * 64 + c);
        }
        asm volatile("cp.async.commit_group;");
    }

    int mbase = (wid & 3) * 32;
    int nbase = (wid >> 2) * 64;
    int g = lane >> 2, t4 = lane & 3;
    float s_total = 0.f;
    int cur = 0;

    while (t < NTILES) {
        int tn = t + NBLK, ti2 = 0, tj2 = 0;
        if (tn < NTILES) {
            map_tile(tn, ti2, tj2);
            waitbits(ti2, tj2);
            __nv_bfloat16* An = Ab + (cur ^ 1) * TILEB;
            __nv_bfloat16* Bn = Bb + (cur ^ 1) * TILEB;
            const __nv_bfloat16* ga = g_zh + (size_t)ti2 * 128 * 64;
            const __nv_bfloat16* gb = g_zh + (size_t)tj2 * 128 * 64;
            #pragma unroll
            for (int it = 0; it < 4; it++) {
                int q = tid + it * 256;
                int r = q >> 3, c = (q & 7) * 8;
                cp16(&An[r * SROW + c], ga + r * 64 + c);
                cp16(&Bn[r * SROW + c], gb + r * 64 + c);
            }
            asm volatile("cp.async.commit_group;");
            asm volatile("cp.async.wait_group 1;");
        } else {
            asm volatile("cp.async.wait_group 0;");
        }
        __syncthreads();                     // current buffer visible to all

        const __nv_bfloat16* As = Ab + cur * TILEB;
        const __nv_bfloat16* Bs = Bb + cur * TILEB;

        float acc[2][8][4];
        #pragma unroll
        for (int mt = 0; mt < 2; mt++)
            #pragma unroll
            for (int nt = 0; nt < 8; nt++)
                #pragma unroll
                for (int q = 0; q < 4; q++) acc[mt][nt][q] = 0.f;

        #pragma unroll
        for (int ks = 0; ks < 4; ks++) {
            int k0 = ks * 16 + t4 * 2;
            uint32_t afr[2][4], bfr[8][2];
            #pragma unroll
            for (int mt = 0; mt < 2; mt++) {
                int r = mbase + mt * 16 + g;
                afr[mt][0] = *(const uint32_t*)&As[r * SROW + k0];
                afr[mt][1] = *(const uint32_t*)&As[(r + 8) * SROW + k0];
                afr[mt][2] = *(const uint32_t*)&As[r * SROW + k0 + 8];
                afr[mt][3] = *(const uint32_t*)&As[(r + 8) * SROW + k0 + 8];
            }
            #pragma unroll
            for (int nt = 0; nt < 8; nt++) {
                int r = nbase + nt * 8 + g;
                bfr[nt][0] = *(const uint32_t*)&Bs[r * SROW + k0];
                bfr[nt][1] = *(const uint32_t*)&Bs[r * SROW + k0 + 8];
            }
            #pragma unroll
            for (int mt = 0; mt < 2; mt++)
                #pragma unroll
                for (int nt = 0; nt < 8; nt++)
                    mma_bf16(acc[mt][nt], afr[mt], bfr[nt]);
        }

        float sA = 0.f, sB = 0.f;
        #pragma unroll
        for (int mt = 0; mt < 2; mt++) {
            #pragma unroll
            for (int half = 0; half < 2; half++) {
                float prodA = 1.f, prodB = 1.f;
                #pragma unroll
                for (int nt = 0; nt < 8; nt++) {
                    float x0 = acc[mt][nt][half * 2];
                    float x1 = acc[mt][nt][half * 2 + 1];
                    sA += fmaxf(x0, 0.f);
                    sB += fmaxf(x1, 0.f);
                    prodA *= (1.f + __expf(-fabsf(x0)));
                    prodB *= (1.f + __expf(-fabsf(x1)));
                }
                sA += __logf(prodA * prodB);
            }
        }
        float wgt = (ti == tj) ? 1.f : 2.f;
        s_total += wgt * (sA + sB);

        __syncthreads();                     // all reads of cur done before refill
        cur ^= 1;
        t = tn;
        ti = ti2;
        tj = tj2;
    }

    red[tid] = s_total;
    __syncthreads();
    #pragma unroll
    for (int o = 128; o; o >>= 1) {
        if (tid < o) red[tid] += red[tid + o];
        __syncthreads();
    }
    if (tid == 0) atomicAdd(&g_sp_sum, (double)red[0]);
}

// ---------------- 9) finalize ----------------
__global__ void k_finalize(float* __restrict__ out) {
    int i = blockIdx.x * blockDim.x + threadIdx.x;
    float recon = (float)((g_edge_sum - g_sp_sum) / (double)N_NODES);
    if (i < N_NODES * OUT_FEAT) out[i] -= recon;
}

// ---------------- launch (fork gather2+edge on stream 0 vs sp on stream 1) ----------------
extern "C" void kernel_launch(void* const* d_in, const int* in_sizes, int n_in,
                              void* d_out, int out_size) {
    const float* h   = (const float*)d_in[0];
    const int*   src = (const int*)d_in[1];
    const int*   dst = (const int*)d_in[2];
    const float* eps = (const float*)d_in[3];
    const float* w0  = (const float*)d_in[4];
    const float* wmu = (const float*)d_in[5];
    const float* wls = (const float*)d_in[6];
    float* out = (float*)d_out;

    static cudaStream_t s1 = nullptr;
    static cudaEvent_t evA = nullptr, evB = nullptr;
    if (!s1) {
        cudaStreamCreateWithFlags(&s1, cudaStreamNonBlocking);
        cudaEventCreateWithFlags(&evA, cudaEventDisableTiming);
        cudaEventCreateWithFlags(&evB, cudaEventDisableTiming);
        cudaFuncSetAttribute(k_sp, cudaFuncAttributeMaxDynamicSharedMemorySize, SP_SMEM);
    }

    k_deg<<<E_EDGES / 256, 256>>>(src);
    k_scan_norm<<<1, 1024>>>();
    k_perm_gemm1<<<1280, 512>>>(src, dst, h, w0);
    k_gather1<<<N_NODES / 8, 256>>>();
    k_gemm2<<<N_NODES / 8, 1024>>>(wmu, wls);

    cudaEventRecord(evA, 0);
    cudaStreamWaitEvent(s1, evA, 0);

    k_gather2<<<N_NODES / 8, 256>>>(eps, out);   // stream 0
    k_edge<<<64, 256>>>(src, dst);               // stream 0 (after gather2)
    k_sp<<<NBLK, 256, SP_SMEM, s1>>>();          // stream 1, flag-synced

    cudaEventRecord(evB, s1);
    cudaStreamWaitEvent(0, evB, 0);
    k_finalize<<<(N_NODES * OUT_FEAT) / 256, 256>>>(out);
}

// round 13
// speedup vs baseline: 1.2778x; 1.2778x over previous
#include <cuda_runtime.h>
#include <cuda_bf16.h>
#include <cstdint>

#define N_NODES 8192
#define IN_FEAT 128
#define OUT_FEAT 64
#define E_EDGES 131072
#define C2 128

// ---------------- device scratch (self-cleaning across graph replays) ----------------
__device__ int    g_deg[N_NODES];          // zero-init; k_scan_norm re-zeroes after use
__device__ int    g_off[N_NODES + 1];
__device__ int    g_cursor[N_NODES];
__device__ int    g_perm[E_EDGES];
__device__ float  g_norm[N_NODES];
__device__ float  g_X0[N_NODES * OUT_FEAT];        // pre-scaled by norm[row]
__device__ float  g_h1n[N_NODES * OUT_FEAT];
__device__ float  g_Y[N_NODES * C2];
__device__ float  g_z[N_NODES * OUT_FEAT];
__device__ __nv_bfloat16 g_zh[N_NODES * OUT_FEAT];
__device__ double g_edge_sum;              // zero-init; k_deg re-zeroes each run
__device__ double g_sp_sum;

// ---------------- 1) degree count (+ reset global sums) ----------------
__global__ void k_deg(const int* __restrict__ src) {
    int e = blockIdx.x * blockDim.x + threadIdx.x;
    if (e == 0) { g_edge_sum = 0.0; g_sp_sum = 0.0; }
    if (e < E_EDGES) atomicAdd(&g_deg[src[e]], 1);
}

// ---------------- 2) scan + norm (+ self-clean g_deg) ----------------
__global__ void k_scan_norm() {
    __shared__ int part[1024];
    int tid = threadIdx.x;
    int base = tid * 8;
    int local[8], dv[8];
    int s = 0;
    #pragma unroll
    for (int j = 0; j < 8; j++) {
        dv[j] = g_deg[base + j];
        local[j] = s;
        s += dv[j];
        g_deg[base + j] = 0;
    }
    part[tid] = s;
    __syncthreads();
    for (int off = 1; off < 1024; off <<= 1) {
        int v = (tid >= off) ? part[tid - off] : 0;
        __syncthreads();
        part[tid] += v;
        __syncthreads();
    }
    int pre = (tid > 0) ? part[tid - 1] : 0;
    #pragma unroll
    for (int j = 0; j < 8; j++) {
        int o = pre + local[j];
        g_off[base + j] = o;
        g_cursor[base + j] = o;
        g_norm[base + j] = rsqrtf((float)(dv[j] < 1 ? 1 : dv[j]));
    }
    if (tid == 1023) g_off[N_NODES] = pre + s;
}

// ---------------- 3) fused: perm scatter + GEMM1 (X0 pre-scaled by norm[row]) ----------------
__global__ void __launch_bounds__(512) k_perm_gemm1(const int* __restrict__ src,
                                                    const int* __restrict__ dst,
                                                    const float* __restrict__ h,
                                                    const float* __restrict__ w0) {
    int tid = threadIdx.x;
    if (blockIdx.x < 1024) {
        __shared__ float ws[IN_FEAT][OUT_FEAT];
        __shared__ float hs[8][IN_FEAT];
        int row0 = blockIdx.x * 8;
        for (int t = tid; t < IN_FEAT * OUT_FEAT; t += 512)
            ws[t >> 6][t & 63] = w0[t];
        for (int t = tid; t < 8 * IN_FEAT; t += 512) {
            int r = t >> 7, k = t & 127;
            hs[r][k] = h[(row0 + r) * IN_FEAT + k];
        }
        __syncthreads();
        int r = tid >> 6, c = tid & 63;
        float acc = 0.f;
        #pragma unroll
        for (int k = 0; k < IN_FEAT; k++) acc = fmaf(hs[r][k], ws[k][c], acc);
        g_X0[(row0 + r) * OUT_FEAT + c] = acc * g_norm[row0 + r];
    } else {
        int e = (blockIdx.x - 1024) * 512 + tid;
        if (e < E_EDGES) {
            int p = atomicAdd(&g_cursor[src[e]], 1);
            g_perm[p] = dst[e];
        }
    }
}

// ---------------- 4) gather 1 (X0 already norm-scaled) ----------------
__global__ void k_gather1() {
    int w = (blockIdx.x * blockDim.x + threadIdx.x) >> 5;
    int lane = threadIdx.x & 31;
    if (w >= N_NODES) return;
    int beg = g_off[w], end = g_off[w + 1];
    float a0 = 0.f, a1 = 0.f;
    int e = beg;
    for (; e + 4 <= end; e += 4) {
        int d0 = g_perm[e], d1 = g_perm[e + 1], d2 = g_perm[e + 2], d3 = g_perm[e + 3];
        float x00 = g_X0[d0 * OUT_FEAT + lane], x01 = g_X0[d0 * OUT_FEAT + lane + 32];
        float x10 = g_X0[d1 * OUT_FEAT + lane], x11 = g_X0[d1 * OUT_FEAT + lane + 32];
        float x20 = g_X0[d2 * OUT_FEAT + lane], x21 = g_X0[d2 * OUT_FEAT + lane + 32];
        float x30 = g_X0[d3 * OUT_FEAT + lane], x31 = g_X0[d3 * OUT_FEAT + lane + 32];
        a0 += x00 + x10 + x20 + x30;
        a1 += x01 + x11 + x21 + x31;
    }
    for (; e < end; e++) {
        int d = g_perm[e];
        a0 += g_X0[d * OUT_FEAT + lane];
        a1 += g_X0[d * OUT_FEAT + lane + 32];
    }
    float nm = g_norm[w];
    g_h1n[w * OUT_FEAT + lane]      = fmaxf(a0 * nm, 0.f) * nm;
    g_h1n[w * OUT_FEAT + lane + 32] = fmaxf(a1 * nm, 0.f) * nm;
}

// ---------------- 5) GEMM 2 ----------------
__global__ void __launch_bounds__(1024) k_gemm2(const float* __restrict__ wmu,
                                                const float* __restrict__ wls) {
    __shared__ float ws[OUT_FEAT][C2];
    __shared__ float hs[8][OUT_FEAT];
    int tid = threadIdx.x;
    int row0 = blockIdx.x * 8;
    for (int t = tid; t < OUT_FEAT * OUT_FEAT; t += 1024) {
        int k = t >> 6, c = t & 63;
        ws[k][c]      = wmu[t];
        ws[k][c + 64] = wls[t];
    }
    for (int t = tid; t < 8 * OUT_FEAT; t += 1024) {
        int r = t >> 6, k = t & 63;
        hs[r][k] = g_h1n[(row0 + r) * OUT_FEAT + k];
    }
    __syncthreads();
    int r = tid >> 7, c = tid & 127;
    float acc = 0.f;
    #pragma unroll
    for (int k = 0; k < OUT_FEAT; k++) acc = fmaf(hs[r][k], ws[k][c], acc);
    g_Y[(row0 + r) * C2 + c] = acc;
}

// ---------------- 6) gather 2 + reparam + KL + bf16 pack (4x unroll) ----------------
__global__ void k_gather2(const float* __restrict__ eps, float* __restrict__ out) {
    int w = (blockIdx.x * blockDim.x + threadIdx.x) >> 5;
    int lane = threadIdx.x & 31;
    if (w >= N_NODES) return;
    int beg = g_off[w], end = g_off[w + 1];
    float m0 = 0.f, m1 = 0.f, l0 = 0.f, l1 = 0.f;
    int e = beg;
    for (; e + 4 <= end; e += 4) {
        int d0 = g_perm[e], d1 = g_perm[e + 1], d2 = g_perm[e + 2], d3 = g_perm[e + 3];
        const float* y0 = &g_Y[d0 * C2];
        const float* y1 = &g_Y[d1 * C2];
        const float* y2 = &g_Y[d2 * C2];
        const float* y3 = &g_Y[d3 * C2];
        float a0 = y0[lane], a1 = y0[lane + 32], a2 = y0[lane + 64], a3 = y0[lane + 96];
        float b0 = y1[lane], b1 = y1[lane + 32], b2 = y1[lane + 64], b3 = y1[lane + 96];
        float c0 = y2[lane], c1 = y2[lane + 32], c2 = y2[lane + 64], c3 = y2[lane + 96];
        float e0 = y3[lane], e1 = y3[lane + 32], e2 = y3[lane + 64], e3 = y3[lane + 96];
        m0 += (a0 + b0) + (c0 + e0);
        m1 += (a1 + b1) + (c1 + e1);
        l0 += (a2 + b2) + (c2 + e2);
        l1 += (a3 + b3) + (c3 + e3);
    }
    for (; e < end; e++) {
        const float* yr = &g_Y[g_perm[e] * C2];
        m0 += yr[lane];      m1 += yr[lane + 32];
        l0 += yr[lane + 64]; l1 += yr[lane + 96];
    }
    float nm = g_norm[w];
    m0 *= nm; m1 *= nm; l0 *= nm; l1 *= nm;
    float s0 = __expf(l0), s1 = __expf(l1);
    float z0 = m0 + s0 * eps[w * OUT_FEAT + lane];
    float z1 = m1 + s1 * eps[w * OUT_FEAT + lane + 32];
    g_z[w * OUT_FEAT + lane]      = z0;
    g_z[w * OUT_FEAT + lane + 32] = z1;
    g_zh[w * OUT_FEAT + lane]      = __float2bfloat16(z0);
    g_zh[w * OUT_FEAT + lane + 32] = __float2bfloat16(z1);
    out[w * OUT_FEAT + lane]      = -l0 + 0.5f * (s0 * s0 + m0 * m0 - 1.f);
    out[w * OUT_FEAT + lane + 32] = -l1 + 0.5f * (s1 * s1 + m1 * m1 - 1.f);
}

// ---------------- 7) persistent double-buffered sp kernel (+edge prologue) ----------------
#define SROW 72
#define TILEB (128 * SROW)                 // bf16 elems per tile buffer (18 KB)
#define NTILES 2080
#define NBLK 296                           // 2 CTAs x 148 SMs, all resident
#define SP_SMEM (4 * TILEB * 2 + 256 * 4)  // 2xA + 2xB + red = 74752 B

__device__ __forceinline__ void cp16(void* sm, const void* gm) {
    uint32_t s = (uint32_t)__cvta_generic_to_shared(sm);
    asm volatile("cp.async.cg.shared.global [%0], [%1], 16;" :: "r"(s), "l"(gm));
}
__device__ __forceinline__ void mma_bf16(float* c, const uint32_t* a, const uint32_t* b) {
    asm volatile(
        "mma.sync.aligned.m16n8k16.row.col.f32.bf16.bf16.f32 "
        "{%0,%1,%2,%3}, {%4,%5,%6,%7}, {%8,%9}, {%0,%1,%2,%3};"
        : "+f"(c[0]), "+f"(c[1]), "+f"(c[2]), "+f"(c[3])
        : "r"(a[0]), "r"(a[1]), "r"(a[2]), "r"(a[3]), "r"(b[0]), "r"(b[1]));
}
__device__ __forceinline__ void map_tile(int b, int& ti, int& tj) {
    ti = (int)((129.0 - sqrt(129.0 * 129.0 - 8.0 * (double)b)) * 0.5);
    if (ti > 63) ti = 63;
    if (ti < 0) ti = 0;
    while (ti < 63 && (ti + 1) * (129 - (ti + 1)) / 2 <= b) ti++;
    while (ti > 0 && ti * (129 - ti) / 2 > b) ti--;
    tj = ti + (b - ti * (129 - ti) / 2);
}

__global__ void __launch_bounds__(256) k_sp_edge(const int* __restrict__ src,
                                                 const int* __restrict__ dst) {
    extern __shared__ __nv_bfloat16 smp[];
    __nv_bfloat16* Ab = smp;                 // [2][TILEB]
    __nv_bfloat16* Bb = smp + 2 * TILEB;     // [2][TILEB]
    float* red = (float*)(smp + 4 * TILEB);

    int tid = threadIdx.x;
    int wid = tid >> 5, lane = tid & 31;

    // prefetch first tile immediately
    int t = blockIdx.x;
    int ti, tj;
    map_tile(t, ti, tj);
    {
        const __nv_bfloat16* ga = g_zh + (size_t)ti * 128 * 64;
        const __nv_bfloat16* gb = g_zh + (size_t)tj * 128 * 64;
        #pragma unroll
        for (int it = 0; it < 4; it++) {
            int q = tid + it * 256;
            int r = q >> 3, c = (q & 7) * 8;
            cp16(&Ab[r * SROW + c], ga + r * 64 + c);
            cp16(&Bb[r * SROW + c], gb + r * 64 + c);
        }
        asm volatile("cp.async.commit_group;");
    }

    // edge term under the first tile's load latency
    {
        float eacc = 0.f;
        for (int e = blockIdx.x * 8 + wid; e < E_EDGES; e += NBLK * 8) {
            int s = src[e], d = dst[e];
            eacc += g_z[s * OUT_FEAT + lane] * g_z[d * OUT_FEAT + lane]
                  + g_z[s * OUT_FEAT + lane + 32] * g_z[d * OUT_FEAT + lane + 32];
        }
        #pragma unroll
        for (int o = 16; o; o >>= 1) eacc += __shfl_xor_sync(0xffffffffu, eacc, o);
        if (lane == 0) red[wid] = eacc;
        __syncthreads();
        if (tid == 0) {
            float s = 0.f;
            #pragma unroll
            for (int i = 0; i < 8; i++) s += red[i];
            atomicAdd(&g_edge_sum, (double)s);
        }
    }

    int mbase = (wid & 3) * 32;
    int nbase = (wid >> 2) * 64;
    int g = lane >> 2, t4 = lane & 3;
    float s_total = 0.f;
    int cur = 0;

    while (t < NTILES) {
        int tn = t + NBLK;
        if (tn < NTILES) {
            int ti2, tj2;
            map_tile(tn, ti2, tj2);
            __nv_bfloat16* An = Ab + (cur ^ 1) * TILEB;
            __nv_bfloat16* Bn = Bb + (cur ^ 1) * TILEB;
            const __nv_bfloat16* ga = g_zh + (size_t)ti2 * 128 * 64;
            const __nv_bfloat16* gb = g_zh + (size_t)tj2 * 128 * 64;
            #pragma unroll
            for (int it = 0; it < 4; it++) {
                int q = tid + it * 256;
                int r = q >> 3, c = (q & 7) * 8;
                cp16(&An[r * SROW + c], ga + r * 64 + c);
                cp16(&Bn[r * SROW + c], gb + r * 64 + c);
            }
            asm volatile("cp.async.commit_group;");
            asm volatile("cp.async.wait_group 1;");
        } else {
            asm volatile("cp.async.wait_group 0;");
        }
        __syncthreads();                     // current buffer visible to all

        const __nv_bfloat16* As = Ab + cur * TILEB;
        const __nv_bfloat16* Bs = Bb + cur * TILEB;

        float acc[2][8][4];
        #pragma unroll
        for (int mt = 0; mt < 2; mt++)
            #pragma unroll
            for (int nt = 0; nt < 8; nt++)
                #pragma unroll
                for (int q = 0; q < 4; q++) acc[mt][nt][q] = 0.f;

        #pragma unroll
        for (int ks = 0; ks < 4; ks++) {
            int k0 = ks * 16 + t4 * 2;
            uint32_t afr[2][4], bfr[8][2];
            #pragma unroll
            for (int mt = 0; mt < 2; mt++) {
                int r = mbase + mt * 16 + g;
                afr[mt][0] = *(const uint32_t*)&As[r * SROW + k0];
                afr[mt][1] = *(const uint32_t*)&As[(r + 8) * SROW + k0];
                afr[mt][2] = *(const uint32_t*)&As[r * SROW + k0 + 8];
                afr[mt][3] = *(const uint32_t*)&As[(r + 8) * SROW + k0 + 8];
            }
            #pragma unroll
            for (int nt = 0; nt < 8; nt++) {
                int r = nbase + nt * 8 + g;
                bfr[nt][0] = *(const uint32_t*)&Bs[r * SROW + k0];
                bfr[nt][1] = *(const uint32_t*)&Bs[r * SROW + k0 + 8];
            }
            #pragma unroll
            for (int mt = 0; mt < 2; mt++)
                #pragma unroll
                for (int nt = 0; nt < 8; nt++)
                    mma_bf16(acc[mt][nt], afr[mt], bfr[nt]);
        }

        // fused softplus; dual prod chains + dual sum accumulators
        float sA = 0.f, sB = 0.f;
        #pragma unroll
        for (int mt = 0; mt < 2; mt++) {
            #pragma unroll
            for (int half = 0; half < 2; half++) {
                float prodA = 1.f, prodB = 1.f;
                #pragma unroll
                for (int nt = 0; nt < 8; nt++) {
                    float x0 = acc[mt][nt][half * 2];
                    float x1 = acc[mt][nt][half * 2 + 1];
                    sA += fmaxf(x0, 0.f);
                    sB += fmaxf(x1, 0.f);
                    prodA *= (1.f + __expf(-fabsf(x0)));
                    prodB *= (1.f + __expf(-fabsf(x1)));
                }
                sA += __logf(prodA * prodB);
            }
        }
        float wgt = (ti == tj) ? 1.f : 2.f;
        s_total += wgt * (sA + sB);

        __syncthreads();                     // all reads of cur done before refill
        cur ^= 1;
        t = tn;
        if (t < NTILES) map_tile(t, ti, tj);
    }

    red[tid] = s_total;
    __syncthreads();
    #pragma unroll
    for (int o = 128; o; o >>= 1) {
        if (tid < o) red[tid] += red[tid + o];
        __syncthreads();
    }
    if (tid == 0) atomicAdd(&g_sp_sum, (double)red[0]);
}

// ---------------- 8) finalize ----------------
__global__ void k_finalize(float* __restrict__ out) {
    int i = blockIdx.x * blockDim.x + threadIdx.x;
    float recon = (float)((g_edge_sum - g_sp_sum) / (double)N_NODES);
    if (i < N_NODES * OUT_FEAT) out[i] -= recon;
}

// ---------------- launch ----------------
extern "C" void kernel_launch(void* const* d_in, const int* in_sizes, int n_in,
                              void* d_out, int out_size) {
    const float* h   = (const float*)d_in[0];
    const int*   src = (const int*)d_in[1];
    const int*   dst = (const int*)d_in[2];
    const float* eps = (const float*)d_in[3];
    const float* w0  = (const float*)d_in[4];
    const float* wmu = (const float*)d_in[5];
    const float* wls = (const float*)d_in[6];
    float* out = (float*)d_out;

    static bool attr_done = false;
    if (!attr_done) {
        cudaFuncSetAttribute(k_sp_edge, cudaFuncAttributeMaxDynamicSharedMemorySize, SP_SMEM);
        attr_done = true;
    }

    k_deg<<<E_EDGES / 256, 256>>>(src);
    k_scan_norm<<<1, 1024>>>();
    k_perm_gemm1<<<1280, 512>>>(src, dst, h, w0);
    k_gather1<<<N_NODES / 8, 256>>>();
    k_gemm2<<<N_NODES / 8, 1024>>>(wmu, wls);
    k_gather2<<<N_NODES / 8, 256>>>(eps, out);
    k_sp_edge<<<NBLK, 256, SP_SMEM>>>(src, dst);
    k_finalize<<<(N_NODES * OUT_FEAT) / 256, 256>>>(out);
}

// round 16
// speedup vs baseline: 1.3019x; 1.0189x over previous
#include <cuda_runtime.h>
#include <cuda_bf16.h>
#include <cstdint>

#define N_NODES 8192
#define IN_FEAT 128
#define OUT_FEAT 64
#define E_EDGES 131072
#define C2 128

// ---------------- device scratch (self-cleaning across graph replays) ----------------
__device__ int    g_deg[N_NODES];          // zero-init; k_scan_norm re-zeroes after use
__device__ int    g_off[N_NODES + 1];
__device__ int    g_cursor[N_NODES];
__device__ int    g_perm[E_EDGES];
__device__ float  g_norm[N_NODES];
__device__ float  g_X0[N_NODES * OUT_FEAT];        // pre-scaled by norm[row]
__device__ float  g_h1n[N_NODES * OUT_FEAT];
__device__ float  g_z[N_NODES * OUT_FEAT];
__device__ __nv_bfloat16 g_zh[N_NODES * OUT_FEAT];
__device__ double g_edge_sum;              // zero-init; k_deg re-zeroes each run
__device__ double g_sp_sum;

// ---------------- 1) degree count (+ reset global sums) ----------------
__global__ void k_deg(const int* __restrict__ src) {
    int e = blockIdx.x * blockDim.x + threadIdx.x;
    if (e == 0) { g_edge_sum = 0.0; g_sp_sum = 0.0; }
    if (e < E_EDGES) atomicAdd(&g_deg[src[e]], 1);
}

// ---------------- 2) scan + norm (+ self-clean g_deg) ----------------
__global__ void k_scan_norm() {
    __shared__ int part[1024];
    int tid = threadIdx.x;
    int base = tid * 8;
    int local[8], dv[8];
    int s = 0;
    #pragma unroll
    for (int j = 0; j < 8; j++) {
        dv[j] = g_deg[base + j];
        local[j] = s;
        s += dv[j];
        g_deg[base + j] = 0;
    }
    part[tid] = s;
    __syncthreads();
    for (int off = 1; off < 1024; off <<= 1) {
        int v = (tid >= off) ? part[tid - off] : 0;
        __syncthreads();
        part[tid] += v;
        __syncthreads();
    }
    int pre = (tid > 0) ? part[tid - 1] : 0;
    #pragma unroll
    for (int j = 0; j < 8; j++) {
        int o = pre + local[j];
        g_off[base + j] = o;
        g_cursor[base + j] = o;
        g_norm[base + j] = rsqrtf((float)(dv[j] < 1 ? 1 : dv[j]));
    }
    if (tid == 1023) g_off[N_NODES] = pre + s;
}

// ---------------- 3) fused: perm scatter + GEMM1 (X0 pre-scaled by norm[row]) ----------------
__global__ void __launch_bounds__(512) k_perm_gemm1(const int* __restrict__ src,
                                                    const int* __restrict__ dst,
                                                    const float* __restrict__ h,
                                                    const float* __restrict__ w0) {
    int tid = threadIdx.x;
    if (blockIdx.x < 1024) {
        __shared__ float ws[IN_FEAT][OUT_FEAT];
        __shared__ float hs[8][IN_FEAT];
        int row0 = blockIdx.x * 8;
        for (int t = tid; t < IN_FEAT * OUT_FEAT; t += 512)
            ws[t >> 6][t & 63] = w0[t];
        for (int t = tid; t < 8 * IN_FEAT; t += 512) {
            int r = t >> 7, k = t & 127;
            hs[r][k] = h[(row0 + r) * IN_FEAT + k];
        }
        __syncthreads();
        int r = tid >> 6, c = tid & 63;
        float acc = 0.f;
        #pragma unroll
        for (int k = 0; k < IN_FEAT; k++) acc = fmaf(hs[r][k], ws[k][c], acc);
        g_X0[(row0 + r) * OUT_FEAT + c] = acc * g_norm[row0 + r];
    } else {
        int e = (blockIdx.x - 1024) * 512 + tid;
        if (e < E_EDGES) {
            int p = atomicAdd(&g_cursor[src[e]], 1);
            g_perm[p] = dst[e];
        }
    }
}

// ---------------- 4) gather 1 (X0 already norm-scaled) ----------------
__global__ void k_gather1() {
    int w = (blockIdx.x * blockDim.x + threadIdx.x) >> 5;
    int lane = threadIdx.x & 31;
    if (w >= N_NODES) return;
    int beg = g_off[w], end = g_off[w + 1];
    float a0 = 0.f, a1 = 0.f;
    int e = beg;
    for (; e + 4 <= end; e += 4) {
        int d0 = g_perm[e], d1 = g_perm[e + 1], d2 = g_perm[e + 2], d3 = g_perm[e + 3];
        float x00 = g_X0[d0 * OUT_FEAT + lane], x01 = g_X0[d0 * OUT_FEAT + lane + 32];
        float x10 = g_X0[d1 * OUT_FEAT + lane], x11 = g_X0[d1 * OUT_FEAT + lane + 32];
        float x20 = g_X0[d2 * OUT_FEAT + lane], x21 = g_X0[d2 * OUT_FEAT + lane + 32];
        float x30 = g_X0[d3 * OUT_FEAT + lane], x31 = g_X0[d3 * OUT_FEAT + lane + 32];
        a0 += x00 + x10 + x20 + x30;
        a1 += x01 + x11 + x21 + x31;
    }
    for (; e < end; e++) {
        int d = g_perm[e];
        a0 += g_X0[d * OUT_FEAT + lane];
        a1 += g_X0[d * OUT_FEAT + lane + 32];
    }
    float nm = g_norm[w];
    g_h1n[w * OUT_FEAT + lane]      = fmaxf(a0 * nm, 0.f) * nm;
    g_h1n[w * OUT_FEAT + lane + 32] = fmaxf(a1 * nm, 0.f) * nm;
}

// ---------------- 5) fused gather2 + W-apply + reparam + KL + bf16 pack ----------------
// Uses linearity: sum_d (h1n[d] @ W) == (sum_d h1n[d]) @ W.  No g_Y, no GEMM2.
__global__ void __launch_bounds__(256) k_g2w(const float* __restrict__ eps,
                                             float* __restrict__ out,
                                             const float* __restrict__ wmu,
                                             const float* __restrict__ wls) {
    __shared__ float ws[OUT_FEAT][C2];           // 32 KB: [w_mu | w_ls]
    __shared__ float rowbuf[8][C2];              // 4 KB: per-warp result row
    int tid = threadIdx.x;
    int wid = tid >> 5, lane = tid & 31;
    for (int t = tid; t < OUT_FEAT * OUT_FEAT; t += 256) {
        int k = t >> 6, c = t & 63;
        ws[k][c]      = wmu[t];
        ws[k][c + 64] = wls[t];
    }
    __syncthreads();

    int w = blockIdx.x * 8 + wid;
    int beg = g_off[w], end = g_off[w + 1];
    float a0 = 0.f, a1 = 0.f;
    int e = beg;
    for (; e + 4 <= end; e += 4) {
        int d0 = g_perm[e], d1 = g_perm[e + 1], d2 = g_perm[e + 2], d3 = g_perm[e + 3];
        float x00 = g_h1n[d0 * OUT_FEAT + lane], x01 = g_h1n[d0 * OUT_FEAT + lane + 32];
        float x10 = g_h1n[d1 * OUT_FEAT + lane], x11 = g_h1n[d1 * OUT_FEAT + lane + 32];
        float x20 = g_h1n[d2 * OUT_FEAT + lane], x21 = g_h1n[d2 * OUT_FEAT + lane + 32];
        float x30 = g_h1n[d3 * OUT_FEAT + lane], x31 = g_h1n[d3 * OUT_FEAT + lane + 32];
        a0 += (x00 + x10) + (x20 + x30);
        a1 += (x01 + x11) + (x21 + x31);
    }
    for (; e < end; e++) {
        int d = g_perm[e];
        a0 += g_h1n[d * OUT_FEAT + lane];
        a1 += g_h1n[d * OUT_FEAT + lane + 32];
    }
    float nm = g_norm[w];
    a0 *= nm; a1 *= nm;                          // scaled gathered row (64 wide)

    // row x matrix: each lane computes 4 consecutive cols of the 128-wide output
    float4 acc = make_float4(0.f, 0.f, 0.f, 0.f);
    #pragma unroll
    for (int k = 0; k < OUT_FEAT; k++) {
        float rk = __shfl_sync(0xffffffffu, (k < 32) ? a0 : a1, k & 31);
        float4 wv = *(const float4*)&ws[k][lane * 4];
        acc.x = fmaf(rk, wv.x, acc.x);
        acc.y = fmaf(rk, wv.y, acc.y);
        acc.z = fmaf(rk, wv.z, acc.z);
        acc.w = fmaf(rk, wv.w, acc.w);
    }
    // redistribute: need mu[lane], mu[lane+32], ls[lane], ls[lane+32]
    *(float4*)&rowbuf[wid][lane * 4] = acc;
    __syncwarp();
    float m0 = rowbuf[wid][lane],      m1 = rowbuf[wid][lane + 32];
    float l0 = rowbuf[wid][lane + 64], l1 = rowbuf[wid][lane + 96];

    float s0 = __expf(l0), s1 = __expf(l1);
    float z0 = m0 + s0 * eps[w * OUT_FEAT + lane];
    float z1 = m1 + s1 * eps[w * OUT_FEAT + lane + 32];
    g_z[w * OUT_FEAT + lane]      = z0;
    g_z[w * OUT_FEAT + lane + 32] = z1;
    g_zh[w * OUT_FEAT + lane]      = __float2bfloat16(z0);
    g_zh[w * OUT_FEAT + lane + 32] = __float2bfloat16(z1);
    out[w * OUT_FEAT + lane]      = -l0 + 0.5f * (s0 * s0 + m0 * m0 - 1.f);
    out[w * OUT_FEAT + lane + 32] = -l1 + 0.5f * (s1 * s1 + m1 * m1 - 1.f);
}

// ---------------- 6) persistent double-buffered sp kernel (+edge prologue) ----------------
#define SROW 72
#define TILEB (128 * SROW)                 // bf16 elems per tile buffer (18 KB)
#define NTILES 2080
#define NBLK 296                           // 2 CTAs x 148 SMs, all resident
#define SP_SMEM (4 * TILEB * 2 + 256 * 4)  // 2xA + 2xB + red = 74752 B

__device__ __forceinline__ void cp16(void* sm, const void* gm) {
    uint32_t s = (uint32_t)__cvta_generic_to_shared(sm);
    asm volatile("cp.async.cg.shared.global [%0], [%1], 16;" :: "r"(s), "l"(gm));
}
__device__ __forceinline__ void mma_bf16(float* c, const uint32_t* a, const uint32_t* b) {
    asm volatile(
        "mma.sync.aligned.m16n8k16.row.col.f32.bf16.bf16.f32 "
        "{%0,%1,%2,%3}, {%4,%5,%6,%7}, {%8,%9}, {%0,%1,%2,%3};"
        : "+f"(c[0]), "+f"(c[1]), "+f"(c[2]), "+f"(c[3])
        : "r"(a[0]), "r"(a[1]), "r"(a[2]), "r"(a[3]), "r"(b[0]), "r"(b[1]));
}
__device__ __forceinline__ void map_tile(int b, int& ti, int& tj) {
    ti = (int)((129.0 - sqrt(129.0 * 129.0 - 8.0 * (double)b)) * 0.5);
    if (ti > 63) ti = 63;
    if (ti < 0) ti = 0;
    while (ti < 63 && (ti + 1) * (129 - (ti + 1)) / 2 <= b) ti++;
    while (ti > 0 && ti * (129 - ti) / 2 > b) ti--;
    tj = ti + (b - ti * (129 - ti) / 2);
}

__global__ void __launch_bounds__(256) k_sp_edge(const int* __restrict__ src,
                                                 const int* __restrict__ dst) {
    extern __shared__ __nv_bfloat16 smp[];
    __nv_bfloat16* Ab = smp;                 // [2][TILEB]
    __nv_bfloat16* Bb = smp + 2 * TILEB;     // [2][TILEB]
    float* red = (float*)(smp + 4 * TILEB);

    int tid = threadIdx.x;
    int wid = tid >> 5, lane = tid & 31;

    // prefetch first tile immediately
    int t = blockIdx.x;
    int ti, tj;
    map_tile(t, ti, tj);
    {
        const __nv_bfloat16* ga = g_zh + (size_t)ti * 128 * 64;
        const __nv_bfloat16* gb = g_zh + (size_t)tj * 128 * 64;
        #pragma unroll
        for (int it = 0; it < 4; it++) {
            int q = tid + it * 256;
            int r = q >> 3, c = (q & 7) * 8;
            cp16(&Ab[r * SROW + c], ga + r * 64 + c);
            cp16(&Bb[r * SROW + c], gb + r * 64 + c);
        }
        asm volatile("cp.async.commit_group;");
    }

    // edge term under the first tile's load latency
    {
        float eacc = 0.f;
        for (int e = blockIdx.x * 8 + wid; e < E_EDGES; e += NBLK * 8) {
            int s = src[e], d = dst[e];
            eacc += g_z[s * OUT_FEAT + lane] * g_z[d * OUT_FEAT + lane]
                  + g_z[s * OUT_FEAT + lane + 32] * g_z[d * OUT_FEAT + lane + 32];
        }
        #pragma unroll
        for (int o = 16; o; o >>= 1) eacc += __shfl_xor_sync(0xffffffffu, eacc, o);
        if (lane == 0) red[wid] = eacc;
        __syncthreads();
        if (tid == 0) {
            float s = 0.f;
            #pragma unroll
            for (int i = 0; i < 8; i++) s += red[i];
            atomicAdd(&g_edge_sum, (double)s);
        }
    }

    int mbase = (wid & 3) * 32;
    int nbase = (wid >> 2) * 64;
    int g = lane >> 2, t4 = lane & 3;
    float s_total = 0.f;
    int cur = 0;

    while (t < NTILES) {
        int tn = t + NBLK;
        if (tn < NTILES) {
            int ti2, tj2;
            map_tile(tn, ti2, tj2);
            __nv_bfloat16* An = Ab + (cur ^ 1) * TILEB;
            __nv_bfloat16* Bn = Bb + (cur ^ 1) * TILEB;
            const __nv_bfloat16* ga = g_zh + (size_t)ti2 * 128 * 64;
            const __nv_bfloat16* gb = g_zh + (size_t)tj2 * 128 * 64;
            #pragma unroll
            for (int it = 0; it < 4; it++) {
                int q = tid + it * 256;
                int r = q >> 3, c = (q & 7) * 8;
                cp16(&An[r * SROW + c], ga + r * 64 + c);
                cp16(&Bn[r * SROW + c], gb + r * 64 + c);
            }
            asm volatile("cp.async.commit_group;");
            asm volatile("cp.async.wait_group 1;");
        } else {
            asm volatile("cp.async.wait_group 0;");
        }
        __syncthreads();                     // current buffer visible to all

        const __nv_bfloat16* As = Ab + cur * TILEB;
        const __nv_bfloat16* Bs = Bb + cur * TILEB;

        float acc[2][8][4];
        #pragma unroll
        for (int mt = 0; mt < 2; mt++)
            #pragma unroll
            for (int nt = 0; nt < 8; nt++)
                #pragma unroll
                for (int q = 0; q < 4; q++) acc[mt][nt][q] = 0.f;

        #pragma unroll
        for (int ks = 0; ks < 4; ks++) {
            int k0 = ks * 16 + t4 * 2;
            uint32_t afr[2][4], bfr[8][2];
            #pragma unroll
            for (int mt = 0; mt < 2; mt++) {
                int r = mbase + mt * 16 + g;
                afr[mt][0] = *(const uint32_t*)&As[r * SROW + k0];
                afr[mt][1] = *(const uint32_t*)&As[(r + 8) * SROW + k0];
                afr[mt][2] = *(const uint32_t*)&As[r * SROW + k0 + 8];
                afr[mt][3] = *(const uint32_t*)&As[(r + 8) * SROW + k0 + 8];
            }
            #pragma unroll
            for (int nt = 0; nt < 8; nt++) {
                int r = nbase + nt * 8 + g;
                bfr[nt][0] = *(const uint32_t*)&Bs[r * SROW + k0];
                bfr[nt][1] = *(const uint32_t*)&Bs[r * SROW + k0 + 8];
            }
            #pragma unroll
            for (int mt = 0; mt < 2; mt++)
                #pragma unroll
                for (int nt = 0; nt < 8; nt++)
                    mma_bf16(acc[mt][nt], afr[mt], bfr[nt]);
        }

        // fused softplus; dual prod chains + dual sum accumulators
        float sA = 0.f, sB = 0.f;
        #pragma unroll
        for (int mt = 0; mt < 2; mt++) {
            #pragma unroll
            for (int half = 0; half < 2; half++) {
                float prodA = 1.f, prodB = 1.f;
                #pragma unroll
                for (int nt = 0; nt < 8; nt++) {
                    float x0 = acc[mt][nt][half * 2];
                    float x1 = acc[mt][nt][half * 2 + 1];
                    sA += fmaxf(x0, 0.f);
                    sB += fmaxf(x1, 0.f);
                    prodA *= (1.f + __expf(-fabsf(x0)));
                    prodB *= (1.f + __expf(-fabsf(x1)));
                }
                sA += __logf(prodA * prodB);
            }
        }
        float wgt = (ti == tj) ? 1.f : 2.f;
        s_total += wgt * (sA + sB);

        __syncthreads();                     // all reads of cur done before refill
        cur ^= 1;
        t = tn;
        if (t < NTILES) map_tile(t, ti, tj);
    }

    red[tid] = s_total;
    __syncthreads();
    #pragma unroll
    for (int o = 128; o; o >>= 1) {
        if (tid < o) red[tid] += red[tid + o];
        __syncthreads();
    }
    if (tid == 0) atomicAdd(&g_sp_sum, (double)red[0]);
}

// ---------------- 7) finalize ----------------
__global__ void k_finalize(float* __restrict__ out) {
    int i = blockIdx.x * blockDim.x + threadIdx.x;
    float recon = (float)((g_edge_sum - g_sp_sum) / (double)N_NODES);
    if (i < N_NODES * OUT_FEAT) out[i] -= recon;
}

// ---------------- launch ----------------
extern "C" void kernel_launch(void* const* d_in, const int* in_sizes, int n_in,
                              void* d_out, int out_size) {
    const float* h   = (const float*)d_in[0];
    const int*   src = (const int*)d_in[1];
    const int*   dst = (const int*)d_in[2];
    const float* eps = (const float*)d_in[3];
    const float* w0  = (const float*)d_in[4];
    const float* wmu = (const float*)d_in[5];
    const float* wls = (const float*)d_in[6];
    float* out = (float*)d_out;

    static bool attr_done = false;
    if (!attr_done) {
        cudaFuncSetAttribute(k_sp_edge, cudaFuncAttributeMaxDynamicSharedMemorySize, SP_SMEM);
        attr_done = true;
    }

    k_deg<<<E_EDGES / 256, 256>>>(src);
    k_scan_norm<<<1, 1024>>>();
    k_perm_gemm1<<<1280, 512>>>(src, dst, h, w0);
    k_gather1<<<N_NODES / 8, 256>>>();
    k_g2w<<<N_NODES / 8, 256>>>(eps, out, wmu, wls);
    k_sp_edge<<<NBLK, 256, SP_SMEM>>>(src, dst);
    k_finalize<<<(N_NODES * OUT_FEAT) / 256, 256>>>(out);
}

// round 17
// speedup vs baseline: 1.3269x; 1.0192x over previous
#include <cuda_runtime.h>
#include <cuda_bf16.h>
#include <cstdint>

#define N_NODES 8192
#define IN_FEAT 128
#define OUT_FEAT 64
#define E_EDGES 131072
#define C2 128
#define NTILES 2080

// ---------------- device scratch (self-cleaning across graph replays) ----------------
__device__ int    g_deg[N_NODES];          // zero-init; k_scan_norm re-zeroes after use
__device__ int    g_off[N_NODES + 1];
__device__ int    g_cursor[N_NODES];
__device__ int    g_perm[E_EDGES];
__device__ float  g_norm[N_NODES];
__device__ float  g_X0[N_NODES * OUT_FEAT];        // pre-scaled by norm[row]
__device__ float  g_h1n[N_NODES * OUT_FEAT];
__device__ float  g_z[N_NODES * OUT_FEAT];
__device__ __nv_bfloat16 g_zh[N_NODES * OUT_FEAT];
__device__ int2   g_tmap[NTILES];          // triangular tile map (ti, tj)
__device__ double g_edge_sum;              // zero-init; k_deg re-zeroes each run
__device__ double g_sp_sum;

// ---------------- 1) degree count (+ reset sums, + build tile LUT) ----------------
__global__ void k_deg(const int* __restrict__ src) {
    int e = blockIdx.x * blockDim.x + threadIdx.x;
    if (e == 0) { g_edge_sum = 0.0; g_sp_sum = 0.0; }
    if (e < NTILES) {
        // fp32 estimate + exact integer correction (same mapping as before, bit-identical)
        int b = e;
        int ti = (int)((129.0f - sqrtf(129.0f * 129.0f - 8.0f * (float)b)) * 0.5f);
        if (ti > 63) ti = 63;
        if (ti < 0) ti = 0;
        while (ti < 63 && (ti + 1) * (129 - (ti + 1)) / 2 <= b) ti++;
        while (ti > 0 && ti * (129 - ti) / 2 > b) ti--;
        g_tmap[e] = make_int2(ti, ti + (b - ti * (129 - ti) / 2));
    }
    if (e < E_EDGES) atomicAdd(&g_deg[src[e]], 1);
}

// ---------------- 2) scan + norm (+ self-clean g_deg) ----------------
__global__ void k_scan_norm() {
    __shared__ int part[1024];
    int tid = threadIdx.x;
    int base = tid * 8;
    int local[8], dv[8];
    int s = 0;
    #pragma unroll
    for (int j = 0; j < 8; j++) {
        dv[j] = g_deg[base + j];
        local[j] = s;
        s += dv[j];
        g_deg[base + j] = 0;
    }
    part[tid] = s;
    __syncthreads();
    for (int off = 1; off < 1024; off <<= 1) {
        int v = (tid >= off) ? part[tid - off] : 0;
        __syncthreads();
        part[tid] += v;
        __syncthreads();
    }
    int pre = (tid > 0) ? part[tid - 1] : 0;
    #pragma unroll
    for (int j = 0; j < 8; j++) {
        int o = pre + local[j];
        g_off[base + j] = o;
        g_cursor[base + j] = o;
        g_norm[base + j] = rsqrtf((float)(dv[j] < 1 ? 1 : dv[j]));
    }
    if (tid == 1023) g_off[N_NODES] = pre + s;
}

// ---------------- 3) fused: perm scatter + GEMM1 (X0 pre-scaled by norm[row]) ----------------
__global__ void __launch_bounds__(512) k_perm_gemm1(const int* __restrict__ src,
                                                    const int* __restrict__ dst,
                                                    const float* __restrict__ h,
                                                    const float* __restrict__ w0) {
    int tid = threadIdx.x;
    if (blockIdx.x < 1024) {
        __shared__ float ws[IN_FEAT][OUT_FEAT];
        __shared__ float hs[8][IN_FEAT];
        int row0 = blockIdx.x * 8;
        for (int t = tid; t < IN_FEAT * OUT_FEAT; t += 512)
            ws[t >> 6][t & 63] = w0[t];
        for (int t = tid; t < 8 * IN_FEAT; t += 512) {
            int r = t >> 7, k = t & 127;
            hs[r][k] = h[(row0 + r) * IN_FEAT + k];
        }
        __syncthreads();
        int r = tid >> 6, c = tid & 63;
        float acc = 0.f;
        #pragma unroll
        for (int k = 0; k < IN_FEAT; k++) acc = fmaf(hs[r][k], ws[k][c], acc);
        g_X0[(row0 + r) * OUT_FEAT + c] = acc * g_norm[row0 + r];
    } else {
        int e = (blockIdx.x - 1024) * 512 + tid;
        if (e < E_EDGES) {
            int p = atomicAdd(&g_cursor[src[e]], 1);
            g_perm[p] = dst[e];
        }
    }
}

// ---------------- 4) gather 1 (X0 already norm-scaled) ----------------
__global__ void k_gather1() {
    int w = (blockIdx.x * blockDim.x + threadIdx.x) >> 5;
    int lane = threadIdx.x & 31;
    if (w >= N_NODES) return;
    int beg = g_off[w], end = g_off[w + 1];
    float a0 = 0.f, a1 = 0.f;
    int e = beg;
    for (; e + 4 <= end; e += 4) {
        int d0 = g_perm[e], d1 = g_perm[e + 1], d2 = g_perm[e + 2], d3 = g_perm[e + 3];
        float x00 = g_X0[d0 * OUT_FEAT + lane], x01 = g_X0[d0 * OUT_FEAT + lane + 32];
        float x10 = g_X0[d1 * OUT_FEAT + lane], x11 = g_X0[d1 * OUT_FEAT + lane + 32];
        float x20 = g_X0[d2 * OUT_FEAT + lane], x21 = g_X0[d2 * OUT_FEAT + lane + 32];
        float x30 = g_X0[d3 * OUT_FEAT + lane], x31 = g_X0[d3 * OUT_FEAT + lane + 32];
        a0 += x00 + x10 + x20 + x30;
        a1 += x01 + x11 + x21 + x31;
    }
    for (; e < end; e++) {
        int d = g_perm[e];
        a0 += g_X0[d * OUT_FEAT + lane];
        a1 += g_X0[d * OUT_FEAT + lane + 32];
    }
    float nm = g_norm[w];
    g_h1n[w * OUT_FEAT + lane]      = fmaxf(a0 * nm, 0.f) * nm;
    g_h1n[w * OUT_FEAT + lane + 32] = fmaxf(a1 * nm, 0.f) * nm;
}

// ---------------- 5) fused gather2 + W-apply + reparam + KL + bf16 pack ----------------
__global__ void __launch_bounds__(256) k_g2w(const float* __restrict__ eps,
                                             float* __restrict__ out,
                                             const float* __restrict__ wmu,
                                             const float* __restrict__ wls) {
    __shared__ float ws[OUT_FEAT][C2];           // 32 KB: [w_mu | w_ls]
    __shared__ float rowbuf[8][C2];              // 4 KB: per-warp result row
    int tid = threadIdx.x;
    int wid = tid >> 5, lane = tid & 31;
    for (int t = tid; t < OUT_FEAT * OUT_FEAT; t += 256) {
        int k = t >> 6, c = t & 63;
        ws[k][c]      = wmu[t];
        ws[k][c + 64] = wls[t];
    }
    __syncthreads();

    int w = blockIdx.x * 8 + wid;
    int beg = g_off[w], end = g_off[w + 1];
    float a0 = 0.f, a1 = 0.f;
    int e = beg;
    for (; e + 4 <= end; e += 4) {
        int d0 = g_perm[e], d1 = g_perm[e + 1], d2 = g_perm[e + 2], d3 = g_perm[e + 3];
        float x00 = g_h1n[d0 * OUT_FEAT + lane], x01 = g_h1n[d0 * OUT_FEAT + lane + 32];
        float x10 = g_h1n[d1 * OUT_FEAT + lane], x11 = g_h1n[d1 * OUT_FEAT + lane + 32];
        float x20 = g_h1n[d2 * OUT_FEAT + lane], x21 = g_h1n[d2 * OUT_FEAT + lane + 32];
        float x30 = g_h1n[d3 * OUT_FEAT + lane], x31 = g_h1n[d3 * OUT_FEAT + lane + 32];
        a0 += (x00 + x10) + (x20 + x30);
        a1 += (x01 + x11) + (x21 + x31);
    }
    for (; e < end; e++) {
        int d = g_perm[e];
        a0 += g_h1n[d * OUT_FEAT + lane];
        a1 += g_h1n[d * OUT_FEAT + lane + 32];
    }
    float nm = g_norm[w];
    a0 *= nm; a1 *= nm;

    float4 acc = make_float4(0.f, 0.f, 0.f, 0.f);
    #pragma unroll
    for (int k = 0; k < OUT_FEAT; k++) {
        float rk = __shfl_sync(0xffffffffu, (k < 32) ? a0 : a1, k & 31);
        float4 wv = *(const float4*)&ws[k][lane * 4];
        acc.x = fmaf(rk, wv.x, acc.x);
        acc.y = fmaf(rk, wv.y, acc.y);
        acc.z = fmaf(rk, wv.z, acc.z);
        acc.w = fmaf(rk, wv.w, acc.w);
    }
    *(float4*)&rowbuf[wid][lane * 4] = acc;
    __syncwarp();
    float m0 = rowbuf[wid][lane],      m1 = rowbuf[wid][lane + 32];
    float l0 = rowbuf[wid][lane + 64], l1 = rowbuf[wid][lane + 96];

    float s0 = __expf(l0), s1 = __expf(l1);
    float z0 = m0 + s0 * eps[w * OUT_FEAT + lane];
    float z1 = m1 + s1 * eps[w * OUT_FEAT + lane + 32];
    g_z[w * OUT_FEAT + lane]      = z0;
    g_z[w * OUT_FEAT + lane + 32] = z1;
    g_zh[w * OUT_FEAT + lane]      = __float2bfloat16(z0);
    g_zh[w * OUT_FEAT + lane + 32] = __float2bfloat16(z1);
    out[w * OUT_FEAT + lane]      = -l0 + 0.5f * (s0 * s0 + m0 * m0 - 1.f);
    out[w * OUT_FEAT + lane + 32] = -l1 + 0.5f * (s1 * s1 + m1 * m1 - 1.f);
}

// ---------------- 6) persistent double-buffered sp kernel (+edge prologue) ----------------
#define SROW 72
#define TILEB (128 * SROW)                 // bf16 elems per tile buffer (18 KB)
#define NBLK 296                           // 2 CTAs x 148 SMs, all resident
#define SP_SMEM (4 * TILEB * 2 + 256 * 4)  // 2xA + 2xB + red = 74752 B

__device__ __forceinline__ void cp16(void* sm, const void* gm) {
    uint32_t s = (uint32_t)__cvta_generic_to_shared(sm);
    asm volatile("cp.async.cg.shared.global [%0], [%1], 16;" :: "r"(s), "l"(gm));
}
__device__ __forceinline__ void mma_bf16(float* c, const uint32_t* a, const uint32_t* b) {
    asm volatile(
        "mma.sync.aligned.m16n8k16.row.col.f32.bf16.bf16.f32 "
        "{%0,%1,%2,%3}, {%4,%5,%6,%7}, {%8,%9}, {%0,%1,%2,%3};"
        : "+f"(c[0]), "+f"(c[1]), "+f"(c[2]), "+f"(c[3])
        : "r"(a[0]), "r"(a[1]), "r"(a[2]), "r"(a[3]), "r"(b[0]), "r"(b[1]));
}

__global__ void __launch_bounds__(256) k_sp_edge(const int* __restrict__ src,
                                                 const int* __restrict__ dst) {
    extern __shared__ __nv_bfloat16 smp[];
    __nv_bfloat16* Ab = smp;                 // [2][TILEB]
    __nv_bfloat16* Bb = smp + 2 * TILEB;     // [2][TILEB]
    float* red = (float*)(smp + 4 * TILEB);

    int tid = threadIdx.x;
    int wid = tid >> 5, lane = tid & 31;

    // prefetch first tile immediately (tile map from LUT — no fp64)
    int t = blockIdx.x;
    int2 tt = g_tmap[t];
    int ti = tt.x, tj = tt.y;
    {
        const __nv_bfloat16* ga = g_zh + (size_t)ti * 128 * 64;
        const __nv_bfloat16* gb = g_zh + (size_t)tj * 128 * 64;
        #pragma unroll
        for (int it = 0; it < 4; it++) {
            int q = tid + it * 256;
            int r = q >> 3, c = (q & 7) * 8;
            cp16(&Ab[r * SROW + c], ga + r * 64 + c);
            cp16(&Bb[r * SROW + c], gb + r * 64 + c);
        }
        asm volatile("cp.async.commit_group;");
    }

    // edge term under the first tile's load latency
    {
        float eacc = 0.f;
        for (int e = blockIdx.x * 8 + wid; e < E_EDGES; e += NBLK * 8) {
            int s = src[e], d = dst[e];
            eacc += g_z[s * OUT_FEAT + lane] * g_z[d * OUT_FEAT + lane]
                  + g_z[s * OUT_FEAT + lane + 32] * g_z[d * OUT_FEAT + lane + 32];
        }
        #pragma unroll
        for (int o = 16; o; o >>= 1) eacc += __shfl_xor_sync(0xffffffffu, eacc, o);
        if (lane == 0) red[wid] = eacc;
        __syncthreads();
        if (tid == 0) {
            float s = 0.f;
            #pragma unroll
            for (int i = 0; i < 8; i++) s += red[i];
            atomicAdd(&g_edge_sum, (double)s);
        }
    }

    int mbase = (wid & 3) * 32;
    int nbase = (wid >> 2) * 64;
    int g = lane >> 2, t4 = lane & 3;
    float s_total = 0.f;
    int cur = 0;

    while (t < NTILES) {
        int tn = t + NBLK;
        int2 tn2 = make_int2(0, 0);
        if (tn < NTILES) {
            tn2 = g_tmap[tn];
            __nv_bfloat16* An = Ab + (cur ^ 1) * TILEB;
            __nv_bfloat16* Bn = Bb + (cur ^ 1) * TILEB;
            const __nv_bfloat16* ga = g_zh + (size_t)tn2.x * 128 * 64;
            const __nv_bfloat16* gb = g_zh + (size_t)tn2.y * 128 * 64;
            #pragma unroll
            for (int it = 0; it < 4; it++) {
                int q = tid + it * 256;
                int r = q >> 3, c = (q & 7) * 8;
                cp16(&An[r * SROW + c], ga + r * 64 + c);
                cp16(&Bn[r * SROW + c], gb + r * 64 + c);
            }
            asm volatile("cp.async.commit_group;");
            asm volatile("cp.async.wait_group 1;");
        } else {
            asm volatile("cp.async.wait_group 0;");
        }
        __syncthreads();                     // current buffer visible to all

        const __nv_bfloat16* As = Ab + cur * TILEB;
        const __nv_bfloat16* Bs = Bb + cur * TILEB;

        float acc[2][8][4];
        #pragma unroll
        for (int mt = 0; mt < 2; mt++)
            #pragma unroll
            for (int nt = 0; nt < 8; nt++)
                #pragma unroll
                for (int q = 0; q < 4; q++) acc[mt][nt][q] = 0.f;

        #pragma unroll
        for (int ks = 0; ks < 4; ks++) {
            int k0 = ks * 16 + t4 * 2;
            uint32_t afr[2][4], bfr[8][2];
            #pragma unroll
            for (int mt = 0; mt < 2; mt++) {
                int r = mbase + mt * 16 + g;
                afr[mt][0] = *(const uint32_t*)&As[r * SROW + k0];
                afr[mt][1] = *(const uint32_t*)&As[(r + 8) * SROW + k0];
                afr[mt][2] = *(const uint32_t*)&As[r * SROW + k0 + 8];
                afr[mt][3] = *(const uint32_t*)&As[(r + 8) * SROW + k0 + 8];
            }
            #pragma unroll
            for (int nt = 0; nt < 8; nt++) {
                int r = nbase + nt * 8 + g;
                bfr[nt][0] = *(const uint32_t*)&Bs[r * SROW + k0];
                bfr[nt][1] = *(const uint32_t*)&Bs[r * SROW + k0 + 8];
            }
            #pragma unroll
            for (int mt = 0; mt < 2; mt++)
                #pragma unroll
                for (int nt = 0; nt < 8; nt++)
                    mma_bf16(acc[mt][nt], afr[mt], bfr[nt]);
        }

        // fused softplus; dual prod chains + dual sum accumulators
        float sA = 0.f, sB = 0.f;
        #pragma unroll
        for (int mt = 0; mt < 2; mt++) {
            #pragma unroll
            for (int half = 0; half < 2; half++) {
                float prodA = 1.f, prodB = 1.f;
                #pragma unroll
                for (int nt = 0; nt < 8; nt++) {
                    float x0 = acc[mt][nt][half * 2];
                    float x1 = acc[mt][nt][half * 2 + 1];
                    sA += fmaxf(x0, 0.f);
                    sB += fmaxf(x1, 0.f);
                    prodA *= (1.f + __expf(-fabsf(x0)));
                    prodB *= (1.f + __expf(-fabsf(x1)));
                }
                sA += __logf(prodA * prodB);
            }
        }
        float wgt = (ti == tj) ? 1.f : 2.f;
        s_total += wgt * (sA + sB);

        __syncthreads();                     // all reads of cur done before refill
        cur ^= 1;
        t = tn;
        ti = tn2.x;
        tj = tn2.y;
    }

    red[tid] = s_total;
    __syncthreads();
    #pragma unroll
    for (int o = 128; o; o >>= 1) {
        if (tid < o) red[tid] += red[tid + o];
        __syncthreads();
    }
    if (tid == 0) atomicAdd(&g_sp_sum, (double)red[0]);
}

// ---------------- 7) finalize ----------------
__global__ void k_finalize(float* __restrict__ out) {
    int i = blockIdx.x * blockDim.x + threadIdx.x;
    float recon = (float)((g_edge_sum - g_sp_sum) / (double)N_NODES);
    if (i < N_NODES * OUT_FEAT) out[i] -= recon;
}

// ---------------- launch ----------------
extern "C" void kernel_launch(void* const* d_in, const int* in_sizes, int n_in,
                              void* d_out, int out_size) {
    const float* h   = (const float*)d_in[0];
    const int*   src = (const int*)d_in[1];
    const int*   dst = (const int*)d_in[2];
    const float* eps = (const float*)d_in[3];
    const float* w0  = (const float*)d_in[4];
    const float* wmu = (const float*)d_in[5];
    const float* wls = (const float*)d_in[6];
    float* out = (float*)d_out;

    static bool attr_done = false;
    if (!attr_done) {
        cudaFuncSetAttribute(k_sp_edge, cudaFuncAttributeMaxDynamicSharedMemorySize, SP_SMEM);
        attr_done = true;
    }

    k_deg<<<E_EDGES / 256, 256>>>(src);
    k_scan_norm<<<1, 1024>>>();
    k_perm_gemm1<<<1280, 512>>>(src, dst, h, w0);
    k_gather1<<<N_NODES / 8, 256>>>();
    k_g2w<<<N_NODES / 8, 256>>>(eps, out, wmu, wls);
    k_sp_edge<<<NBLK, 256, SP_SMEM>>>(src, dst);
    k_finalize<<<(N_NODES * OUT_FEAT) / 256, 256>>>(out);
}